// round 11
// baseline (speedup 1.0000x reference)
#include <cuda_runtime.h>
#include <cuda_bf16.h>
#include <cstdint>

// ---------------------------------------------------------------------------
// QRN: 3-layer bidirectional quasi-RNN, T=65536, D=256.
// mma.sync (HMMA bf16, fp32 accum) — tcgen05 unavailable (plain sm_103 PTX
// target, verified R9). 3-term bf16 split (hi*hi + hi*lo + lo*hi) gives
// fp32-grade accuracy. cp.async 2-stage pipelined GEMM; gate fused into the
// h-GEMM epilogue. Layer-0: q constant -> folded weights.
// Output: h_fwd[T-1] of last layer (layer-2 backward pass is dead code).
// ---------------------------------------------------------------------------

#define TT 65536
#define DD 256
#define CH 256
#define NC (TT / CH)

typedef __nv_bfloat16 bf16;

// ----- scratch (device globals; no runtime allocation allowed) -----
__device__ float g_a[TT * DD];
__device__ float g_b[TT * DD];
__device__ float g_hf[TT * DD];
__device__ float g_zpre[TT * DD];
__device__ float g_Aagg[NC * DD];
__device__ float g_Bagg[NC * DD];
__device__ float g_pref[NC * DD];
__device__ float g_Wz0f[DD * DD];
__device__ float g_ch0f[DD];
__device__ float g_Wz0b[DD * DD];
__device__ float g_ch0b[DD];

// bf16 split operands
__device__ bf16 g_xcat_h[TT * 512];  // [t][0:256]=x, [256:512]=q (per layer)
__device__ bf16 g_xcat_l[TT * 512];
__device__ bf16 g_xq_h[TT * DD];     // x*q (layers >= 1)
__device__ bf16 g_xq_l[TT * DD];

// transposed K-major bf16 weights: [n][k]
__device__ bf16 g_Wz0fT_h[DD * DD], g_Wz0fT_l[DD * DD];
__device__ bf16 g_Wz0bT_h[DD * DD], g_Wz0bT_l[DD * DD];
__device__ bf16 g_Wt0fT_h[DD * DD], g_Wt0fT_l[DD * DD];   // layer-0 Wh top
__device__ bf16 g_Wt0bT_h[DD * DD], g_Wt0bT_l[DD * DD];
__device__ bf16 g_WzT_h[3 * DD * DD], g_WzT_l[3 * DD * DD];      // f1,f2,b1
__device__ bf16 g_WhT_h[3 * DD * 512], g_WhT_l[3 * DD * 512];    // f1,f2,b1

__device__ __forceinline__ float fast_sigmoid(float x) {
    return 1.0f / (1.0f + __expf(-x));
}
__device__ __forceinline__ float fast_tanh(float x) {
    return 1.0f - 2.0f / (__expf(2.0f * x) + 1.0f);
}

__device__ __forceinline__ uint32_t smem_u32(const void* p) {
    uint32_t a;
    asm("{ .reg .u64 t; cvta.to.shared.u64 t, %1; cvt.u32.u64 %0, t; }"
        : "=r"(a) : "l"(p));
    return a;
}
__device__ __forceinline__ void ldmx4(uint32_t* r, uint32_t addr) {
    asm volatile(
        "ldmatrix.sync.aligned.m8n8.x4.shared.b16 {%0,%1,%2,%3}, [%4];"
        : "=r"(r[0]), "=r"(r[1]), "=r"(r[2]), "=r"(r[3]) : "r"(addr));
}
__device__ __forceinline__ void mma_bf16(float* c, const uint32_t* a,
                                         const uint32_t* b) {
    asm volatile(
        "mma.sync.aligned.m16n8k16.row.col.f32.bf16.bf16.f32 "
        "{%0,%1,%2,%3}, {%4,%5,%6,%7}, {%8,%9}, {%0,%1,%2,%3};"
        : "+f"(c[0]), "+f"(c[1]), "+f"(c[2]), "+f"(c[3])
        : "r"(a[0]), "r"(a[1]), "r"(a[2]), "r"(a[3]), "r"(b[0]), "r"(b[1]));
}
#define CP_ASYNC(dst, src) \
    asm volatile("cp.async.cg.shared.global [%0], [%1], 16;" \
                 :: "r"(dst), "l"(src))
#define CP_COMMIT() asm volatile("cp.async.commit_group;" ::: "memory")
#define CP_WAIT(n) asm volatile("cp.async.wait_group %0;" :: "n"(n) : "memory")

// ---------------------------------------------------------------------------
// bf16-split GEMM: C[M,256] = A[M,K] @ B[256,K]^T, 3-term hi/lo.
// CTA tile 128x128 (grid.y=2 covers N=256), BK=32, 8 warps of 32x64.
// 2-stage cp.async pipeline. smem stride 40 bf16 (80B): conflict-free
// ldmatrix (row offsets mod 128B = {0,80,32,112,64,16,96,48}).
// FUSE=0: write preact to Cz.  FUSE=1: read Cz as zpre, gate, write g_a/g_b.
// ---------------------------------------------------------------------------
#define GSTR 40
#define SOFF_AH 0
#define SOFF_AL (128 * GSTR)
#define SOFF_BH (2 * 128 * GSTR)
#define SOFF_BL (3 * 128 * GSTR)
#define STAGE_BF16 (4 * 128 * GSTR)             // 20480 bf16
#define GEMM_SMEM (2 * STAGE_BF16 * 2)          // 81920 bytes

__device__ __forceinline__ void load_chunk_async(
    uint32_t sstage, const bf16* __restrict__ Ah, const bf16* __restrict__ Al,
    int lda, const bf16* __restrict__ Bh, const bf16* __restrict__ Bl, int ldb,
    int m0, int n0, int k0, int tid) {
#pragma unroll
    for (int l = 0; l < 2; l++) {
        const int i = tid + l * 256;       // 512 x 16B per array
        const int r = i >> 2, c16 = i & 3; // 4 x 16B per 64B row
        const uint32_t so = (uint32_t)(r * GSTR + c16 * 8) * 2;
        const size_t ga = (size_t)(m0 + r) * lda + k0 + c16 * 8;
        const size_t gb = (size_t)(n0 + r) * ldb + k0 + c16 * 8;
        CP_ASYNC(sstage + SOFF_AH * 2 + so, Ah + ga);
        CP_ASYNC(sstage + SOFF_AL * 2 + so, Al + ga);
        CP_ASYNC(sstage + SOFF_BH * 2 + so, Bh + gb);
        CP_ASYNC(sstage + SOFF_BL * 2 + so, Bl + gb);
    }
}

template <int FUSE>
__global__ __launch_bounds__(256) void qrn_gemm_mma(
    const bf16* __restrict__ Ah, const bf16* __restrict__ Al, int lda, int K,
    const bf16* __restrict__ Bh, const bf16* __restrict__ Bl,
    float* __restrict__ Cz,                       // FUSE=0: out ; FUSE=1: zpre in
    const float* __restrict__ bz, const float* __restrict__ bh) {
    extern __shared__ bf16 sm[];
    const uint32_t sbase = smem_u32(sm);
    const int tid = threadIdx.x;
    const int wid = tid >> 5;
    const int lane = tid & 31;
    const int m0 = blockIdx.x * 128;
    const int n0 = blockIdx.y * 128;
    const int wm = (wid & 3) * 32;   // warp m-offset
    const int wn = (wid >> 2) * 64;  // warp n-offset

    float c[2][8][4];
#pragma unroll
    for (int mt = 0; mt < 2; mt++)
#pragma unroll
        for (int nt = 0; nt < 8; nt++)
#pragma unroll
            for (int j = 0; j < 4; j++) c[mt][nt][j] = 0.0f;

    const int la_row = (lane & 7) + ((lane >> 3) & 1) * 8;
    const int la_k = (lane >> 4) * 8;
    const int lb_row = (lane & 7) + (lane >> 4) * 8;
    const int lb_k = ((lane >> 3) & 1) * 8;

    const int nch = K >> 5;
    // prologue: prefetch chunk 0 into stage 0
    load_chunk_async(sbase, Ah, Al, lda, Bh, Bl, K, m0, n0, 0, tid);
    CP_COMMIT();

    for (int ch = 0; ch < nch; ch++) {
        if (ch + 1 < nch) {
            load_chunk_async(sbase + ((ch + 1) & 1) * STAGE_BF16 * 2, Ah, Al,
                             lda, Bh, Bl, K, m0, n0, (ch + 1) * 32, tid);
            CP_COMMIT();
            CP_WAIT(1);
        } else {
            CP_WAIT(0);
        }
        __syncthreads();

        const uint32_t st = sbase + (ch & 1) * STAGE_BF16 * 2;
#pragma unroll
        for (int ks = 0; ks < 32; ks += 16) {
            uint32_t ah[2][4], al[2][4], bh2[8][2], bl2[8][2];
#pragma unroll
            for (int mt = 0; mt < 2; mt++) {
                const uint32_t ra =
                    st + ((wm + mt * 16 + la_row) * GSTR + ks + la_k) * 2;
                ldmx4(ah[mt], ra + SOFF_AH * 2);
                ldmx4(al[mt], ra + SOFF_AL * 2);
            }
#pragma unroll
            for (int ntp = 0; ntp < 4; ntp++) {
                const uint32_t rb =
                    st + ((wn + ntp * 16 + lb_row) * GSTR + ks + lb_k) * 2;
                uint32_t t[4];
                ldmx4(t, rb + SOFF_BH * 2);
                bh2[ntp * 2][0] = t[0]; bh2[ntp * 2][1] = t[1];
                bh2[ntp * 2 + 1][0] = t[2]; bh2[ntp * 2 + 1][1] = t[3];
                ldmx4(t, rb + SOFF_BL * 2);
                bl2[ntp * 2][0] = t[0]; bl2[ntp * 2][1] = t[1];
                bl2[ntp * 2 + 1][0] = t[2]; bl2[ntp * 2 + 1][1] = t[3];
            }
#pragma unroll
            for (int mt = 0; mt < 2; mt++)
#pragma unroll
                for (int nt = 0; nt < 8; nt++) {
                    mma_bf16(c[mt][nt], ah[mt], bh2[nt]);
                    mma_bf16(c[mt][nt], al[mt], bh2[nt]);
                    mma_bf16(c[mt][nt], ah[mt], bl2[nt]);
                }
        }
        __syncthreads();  // all warps done with stage ch&1 before re-prefetch
    }

    // epilogue
#pragma unroll
    for (int mt = 0; mt < 2; mt++) {
#pragma unroll
        for (int nt = 0; nt < 8; nt++) {
            const int gr0 = m0 + wm + mt * 16 + (lane >> 2);
            const int gc = n0 + wn + nt * 8 + (lane & 3) * 2;
#pragma unroll
            for (int half = 0; half < 2; half++) {
                const int gr = gr0 + half * 8;
                const float v0 = c[mt][nt][half * 2];
                const float v1 = c[mt][nt][half * 2 + 1];
                if (FUSE == 0) {
                    *(float2*)&Cz[(size_t)gr * DD + gc] = make_float2(v0, v1);
                } else {
                    const float2 zp = *(const float2*)&Cz[(size_t)gr * DD + gc];
                    const float z0 = fast_sigmoid(zp.x + bz[gc]);
                    const float z1 = fast_sigmoid(zp.y + bz[gc + 1]);
                    const float t0 = fast_tanh(v0 + bh[gc]);
                    const float t1 = fast_tanh(v1 + bh[gc + 1]);
                    *(float2*)&g_a[(size_t)gr * DD + gc] =
                        make_float2(1.0f - z0, 1.0f - z1);
                    *(float2*)&g_b[(size_t)gr * DD + gc] =
                        make_float2(z0 * t0, z1 * t1);
                }
            }
        }
    }
}

// ---------------------------------------------------------------------------
// Layer-0 folding + conversions
// ---------------------------------------------------------------------------
__global__ void fold_wz_kernel(const float* __restrict__ question,
                               const float* __restrict__ Wz,
                               float* __restrict__ Wzp) {
    const int k = blockIdx.x, n = threadIdx.x;
    Wzp[k * DD + n] = question[k] * Wz[k * DD + n];
}
// ch[n] = bh[n] + sum_k q[k]*Whbot[k][n].  Block = (32 n, 8 k-partials),
// grid = DD/32; coalesced loads, smem reduction (was grid=1 latency chain).
__global__ void fold_ch_kernel(const float* __restrict__ question,
                               const float* __restrict__ Whbot,
                               const float* __restrict__ bh,
                               float* __restrict__ ch) {
    __shared__ float red[8][32];
    const int nl = threadIdx.x & 31;
    const int kp = threadIdx.x >> 5;
    const int n = blockIdx.x * 32 + nl;
    float s = 0.0f;
    for (int k = kp; k < DD; k += 8)
        s = fmaf(question[k], Whbot[k * DD + n], s);
    red[kp][nl] = s;
    __syncthreads();
    if (kp == 0) {
        float t = bh[n];
#pragma unroll
        for (int j = 0; j < 8; j++) t += red[j][nl];
        ch[n] = t;
    }
}
// W [K][256] fp32 -> hi/lo [256][K] bf16 (transpose + split). grid=K, block=256.
__global__ void convT_kernel(const float* __restrict__ W, bf16* __restrict__ oh,
                             bf16* __restrict__ ol, int K) {
    const int k = blockIdx.x, n = threadIdx.x;
    const float v = W[k * DD + n];
    const bf16 h = __float2bfloat16(v);
    oh[(size_t)n * K + k] = h;
    ol[(size_t)n * K + k] = __float2bfloat16(v - __bfloat162float(h));
}
__global__ void split_x_kernel(const float* __restrict__ story) {
    const int idx = blockIdx.x * blockDim.x + threadIdx.x;
    const int t = idx >> 8, d = idx & 255;
    const float v = story[idx];
    const bf16 h = __float2bfloat16(v);
    g_xcat_h[(size_t)t * 512 + d] = h;
    g_xcat_l[(size_t)t * 512 + d] = __float2bfloat16(v - __bfloat162float(h));
}

// ---------------------------------------------------------------------------
// Scans (3-pass chunked linear recurrence; channel = threadIdx.x)
// ---------------------------------------------------------------------------
template <int REV>
__global__ void scan1_kernel() {
    const int c = blockIdx.x, d = threadIdx.x;
    float Ar = 1.0f, Br = 0.0f;
    const int base = c * CH;
#pragma unroll 4
    for (int i = 0; i < CH; i++) {
        const int t = base + (REV ? (CH - 1 - i) : i);
        const float a = g_a[(size_t)t * DD + d];
        const float b = g_b[(size_t)t * DD + d];
        Br = fmaf(a, Br, b);
        Ar *= a;
    }
    g_Aagg[c * DD + d] = Ar;
    g_Bagg[c * DD + d] = Br;
}

#define S2_BATCH 16
template <int REV>
__global__ void scan2_kernel() {
    const int d = blockIdx.x * 32 + threadIdx.x;
    float h = 0.0f;
    for (int ci0 = 0; ci0 < NC; ci0 += S2_BATCH) {
        float A[S2_BATCH], B[S2_BATCH];
#pragma unroll
        for (int j = 0; j < S2_BATCH; j++) {
            const int c = REV ? (NC - 1 - (ci0 + j)) : (ci0 + j);
            A[j] = g_Aagg[c * DD + d];
            B[j] = g_Bagg[c * DD + d];
        }
#pragma unroll
        for (int j = 0; j < S2_BATCH; j++) {
            const int c = REV ? (NC - 1 - (ci0 + j)) : (ci0 + j);
            g_pref[c * DD + d] = h;
            h = fmaf(A[j], h, B[j]);
        }
    }
}

__global__ void scan3_fwd_kernel() {
    const int c = blockIdx.x, d = threadIdx.x;
    float h = g_pref[c * DD + d];
    const int base = c * CH;
#pragma unroll 4
    for (int i = 0; i < CH; i++) {
        const int t = base + i;
        h = fmaf(g_a[(size_t)t * DD + d], h, g_b[(size_t)t * DD + d]);
        g_hf[(size_t)t * DD + d] = h;
    }
}

// Backward scan fused with next-layer operand prep:
//   q = h_bwd + h_fwd -> xcat[:,256+d] hi/lo ; xq = story*q -> xq hi/lo
__global__ void scan3_bwd_conv_kernel(const float* __restrict__ story) {
    const int c = blockIdx.x, d = threadIdx.x;
    float h = g_pref[c * DD + d];
    const int base = c * CH;
#pragma unroll 4
    for (int i = CH - 1; i >= 0; i--) {
        const int t = base + i;
        h = fmaf(g_a[(size_t)t * DD + d], h, g_b[(size_t)t * DD + d]);
        const float q = h + g_hf[(size_t)t * DD + d];
        const bf16 qh = __float2bfloat16(q);
        g_xcat_h[(size_t)t * 512 + 256 + d] = qh;
        g_xcat_l[(size_t)t * 512 + 256 + d] =
            __float2bfloat16(q - __bfloat162float(qh));
        const float p = story[(size_t)t * DD + d] * q;
        const bf16 ph = __float2bfloat16(p);
        g_xq_h[(size_t)t * DD + d] = ph;
        g_xq_l[(size_t)t * DD + d] =
            __float2bfloat16(p - __bfloat162float(ph));
    }
}

__global__ void final_kernel(float* __restrict__ out) {
    const int d = blockIdx.x * 32 + threadIdx.x;
    float h = 0.0f;
    for (int c0 = 0; c0 < NC; c0 += S2_BATCH) {
        float A[S2_BATCH], B[S2_BATCH];
#pragma unroll
        for (int j = 0; j < S2_BATCH; j++) {
            A[j] = g_Aagg[(c0 + j) * DD + d];
            B[j] = g_Bagg[(c0 + j) * DD + d];
        }
#pragma unroll
        for (int j = 0; j < S2_BATCH; j++) h = fmaf(A[j], h, B[j]);
    }
    out[d] = h;
}

// ---------------------------------------------------------------------------
extern "C" void kernel_launch(void* const* d_in, const int* in_sizes, int n_in,
                              void* d_out, int out_size) {
    const float* story = (const float*)d_in[0];
    const float* question = (const float*)d_in[1];
    const float* Wzf = (const float*)d_in[2];
    const float* bzf = (const float*)d_in[3];
    const float* Whf = (const float*)d_in[4];
    const float* bhf = (const float*)d_in[5];
    const float* Wzb = (const float*)d_in[6];
    const float* bzb = (const float*)d_in[7];
    const float* Whb = (const float*)d_in[8];
    const float* bhb = (const float*)d_in[9];
    float* out = (float*)d_out;

    cudaFuncSetAttribute(qrn_gemm_mma<0>,
                         cudaFuncAttributeMaxDynamicSharedMemorySize, GEMM_SMEM);
    cudaFuncSetAttribute(qrn_gemm_mma<1>,
                         cudaFuncAttributeMaxDynamicSharedMemorySize, GEMM_SMEM);

#define SYM(v, s) void* v; cudaGetSymbolAddress(&v, s)
    SYM(pWz0f, g_Wz0f); SYM(pch0f, g_ch0f);
    SYM(pWz0b, g_Wz0b); SYM(pch0b, g_ch0b);
    SYM(pXh, g_xcat_h); SYM(pXl, g_xcat_l);
    SYM(pQh, g_xq_h);   SYM(pQl, g_xq_l);
    SYM(pZp, g_zpre);
    SYM(pWz0fTh, g_Wz0fT_h); SYM(pWz0fTl, g_Wz0fT_l);
    SYM(pWz0bTh, g_Wz0bT_h); SYM(pWz0bTl, g_Wz0bT_l);
    SYM(pWt0fTh, g_Wt0fT_h); SYM(pWt0fTl, g_Wt0fT_l);
    SYM(pWt0bTh, g_Wt0bT_h); SYM(pWt0bTl, g_Wt0bT_l);
    SYM(pWzTh, g_WzT_h); SYM(pWzTl, g_WzT_l);
    SYM(pWhTh, g_WhT_h); SYM(pWhTl, g_WhT_l);
#undef SYM
#define BF(p) ((bf16*)(p))
#define F32(p) ((float*)(p))

    // ---- folding + conversions ----
    fold_wz_kernel<<<DD, DD>>>(question, Wzf, F32(pWz0f));
    fold_ch_kernel<<<DD / 32, 256>>>(question, Whf + DD * DD, bhf, F32(pch0f));
    fold_wz_kernel<<<DD, DD>>>(question, Wzb, F32(pWz0b));
    fold_ch_kernel<<<DD / 32, 256>>>(question, Whb + DD * DD, bhb, F32(pch0b));

    convT_kernel<<<DD, DD>>>(F32(pWz0f), BF(pWz0fTh), BF(pWz0fTl), DD);
    convT_kernel<<<DD, DD>>>(F32(pWz0b), BF(pWz0bTh), BF(pWz0bTl), DD);
    convT_kernel<<<DD, DD>>>(Whf, BF(pWt0fTh), BF(pWt0fTl), DD);
    convT_kernel<<<DD, DD>>>(Whb, BF(pWt0bTh), BF(pWt0bTl), DD);
    convT_kernel<<<DD, DD>>>(Wzf + 1 * DD * DD, BF(pWzTh) + 0 * DD * DD,
                             BF(pWzTl) + 0 * DD * DD, DD);
    convT_kernel<<<DD, DD>>>(Wzf + 2 * DD * DD, BF(pWzTh) + 1 * DD * DD,
                             BF(pWzTl) + 1 * DD * DD, DD);
    convT_kernel<<<DD, DD>>>(Wzb + 1 * DD * DD, BF(pWzTh) + 2 * DD * DD,
                             BF(pWzTl) + 2 * DD * DD, DD);
    convT_kernel<<<512, DD>>>(Whf + 1 * 2 * DD * DD, BF(pWhTh) + 0 * DD * 512,
                              BF(pWhTl) + 0 * DD * 512, 512);
    convT_kernel<<<512, DD>>>(Whf + 2 * 2 * DD * DD, BF(pWhTh) + 1 * DD * 512,
                              BF(pWhTl) + 1 * DD * 512, 512);
    convT_kernel<<<512, DD>>>(Whb + 1 * 2 * DD * DD, BF(pWhTh) + 2 * DD * 512,
                              BF(pWhTl) + 2 * DD * 512, 512);
    split_x_kernel<<<TT * DD / 256, 256>>>(story);

    const dim3 gg(TT / 128, 2);

    // ---- layer 0 fwd (A = x slice of xcat, lda=512, K=256) ----
    qrn_gemm_mma<0><<<gg, 256, GEMM_SMEM>>>(BF(pXh), BF(pXl), 512, 256,
                                            BF(pWz0fTh), BF(pWz0fTl),
                                            F32(pZp), nullptr, nullptr);
    qrn_gemm_mma<1><<<gg, 256, GEMM_SMEM>>>(BF(pXh), BF(pXl), 512, 256,
                                            BF(pWt0fTh), BF(pWt0fTl),
                                            F32(pZp), bzf, F32(pch0f));
    scan1_kernel<0><<<NC, DD>>>();
    scan2_kernel<0><<<8, 32>>>();
    scan3_fwd_kernel<<<NC, DD>>>();
    // ---- layer 0 bwd ----
    qrn_gemm_mma<0><<<gg, 256, GEMM_SMEM>>>(BF(pXh), BF(pXl), 512, 256,
                                            BF(pWz0bTh), BF(pWz0bTl),
                                            F32(pZp), nullptr, nullptr);
    qrn_gemm_mma<1><<<gg, 256, GEMM_SMEM>>>(BF(pXh), BF(pXl), 512, 256,
                                            BF(pWt0bTh), BF(pWt0bTl),
                                            F32(pZp), bzb, F32(pch0b));
    scan1_kernel<1><<<NC, DD>>>();
    scan2_kernel<1><<<8, 32>>>();
    scan3_bwd_conv_kernel<<<NC, DD>>>(story);  // q, xq hi/lo for layer 1

    // ---- layer 1 fwd ----
    qrn_gemm_mma<0><<<gg, 256, GEMM_SMEM>>>(
        BF(pQh), BF(pQl), 256, 256,
        BF(pWzTh) + 0 * DD * DD, BF(pWzTl) + 0 * DD * DD,
        F32(pZp), nullptr, nullptr);
    qrn_gemm_mma<1><<<gg, 256, GEMM_SMEM>>>(
        BF(pXh), BF(pXl), 512, 512,
        BF(pWhTh) + 0 * DD * 512, BF(pWhTl) + 0 * DD * 512,
        F32(pZp), bzf + DD, bhf + DD);
    scan1_kernel<0><<<NC, DD>>>();
    scan2_kernel<0><<<8, 32>>>();
    scan3_fwd_kernel<<<NC, DD>>>();
    // ---- layer 1 bwd ----
    qrn_gemm_mma<0><<<gg, 256, GEMM_SMEM>>>(
        BF(pQh), BF(pQl), 256, 256,
        BF(pWzTh) + 2 * DD * DD, BF(pWzTl) + 2 * DD * DD,
        F32(pZp), nullptr, nullptr);
    qrn_gemm_mma<1><<<gg, 256, GEMM_SMEM>>>(
        BF(pXh), BF(pXl), 512, 512,
        BF(pWhTh) + 2 * DD * 512, BF(pWhTl) + 2 * DD * 512,
        F32(pZp), bzb + DD, bhb + DD);
    scan1_kernel<1><<<NC, DD>>>();
    scan2_kernel<1><<<8, 32>>>();
    scan3_bwd_conv_kernel<<<NC, DD>>>(story);  // q, xq for layer 2

    // ---- layer 2 fwd (only h_fwd[T-1] needed) ----
    qrn_gemm_mma<0><<<gg, 256, GEMM_SMEM>>>(
        BF(pQh), BF(pQl), 256, 256,
        BF(pWzTh) + 1 * DD * DD, BF(pWzTl) + 1 * DD * DD,
        F32(pZp), nullptr, nullptr);
    qrn_gemm_mma<1><<<gg, 256, GEMM_SMEM>>>(
        BF(pXh), BF(pXl), 512, 512,
        BF(pWhTh) + 1 * DD * 512, BF(pWhTl) + 1 * DD * 512,
        F32(pZp), bzf + 2 * DD, bhf + 2 * DD);
    scan1_kernel<0><<<NC, DD>>>();
    final_kernel<<<8, 32>>>(out);
}

// round 12
// speedup vs baseline: 1.1119x; 1.1119x over previous
#include <cuda_runtime.h>
#include <cuda_bf16.h>
#include <cstdint>

// ---------------------------------------------------------------------------
// QRN: 3-layer bidirectional quasi-RNN, T=65536, D=256.
// mma.sync (HMMA bf16, fp32 accum) — tcgen05 unavailable (plain sm_103 PTX
// target, verified R9). 3-term bf16 split (hi*hi + hi*lo + lo*hi) gives
// fp32-grade accuracy. Synchronous-load GEMM (cp.async pipeline regressed in
// R11: register-limited occupancy), gate fused into the h-GEMM epilogue.
// Layer-0: q constant -> folded weights.
// Prolog is exactly 3 launches so launch #4 (ncu capture slot) = z-GEMM.
// Output: h_fwd[T-1] of last layer (layer-2 backward pass is dead code).
// ---------------------------------------------------------------------------

#define TT 65536
#define DD 256
#define CH 256
#define NC (TT / CH)

typedef __nv_bfloat16 bf16;

// ----- scratch (device globals; no runtime allocation allowed) -----
__device__ float g_a[TT * DD];
__device__ float g_b[TT * DD];
__device__ float g_hf[TT * DD];
__device__ float g_zpre[TT * DD];
__device__ float g_Aagg[NC * DD];
__device__ float g_Bagg[NC * DD];
__device__ float g_pref[NC * DD];
__device__ float g_Wz0f[DD * DD];
__device__ float g_ch0f[DD];
__device__ float g_Wz0b[DD * DD];
__device__ float g_ch0b[DD];

// bf16 split operands
__device__ bf16 g_xcat_h[TT * 512];  // [t][0:256]=x, [256:512]=q (per layer)
__device__ bf16 g_xcat_l[TT * 512];
__device__ bf16 g_xq_h[TT * DD];     // x*q (layers >= 1)
__device__ bf16 g_xq_l[TT * DD];

// transposed K-major bf16 weights: [n][k]
__device__ bf16 g_Wz0fT_h[DD * DD], g_Wz0fT_l[DD * DD];
__device__ bf16 g_Wz0bT_h[DD * DD], g_Wz0bT_l[DD * DD];
__device__ bf16 g_Wt0fT_h[DD * DD], g_Wt0fT_l[DD * DD];   // layer-0 Wh top
__device__ bf16 g_Wt0bT_h[DD * DD], g_Wt0bT_l[DD * DD];
__device__ bf16 g_WzT_h[3 * DD * DD], g_WzT_l[3 * DD * DD];      // f1,f2,b1
__device__ bf16 g_WhT_h[3 * DD * 512], g_WhT_l[3 * DD * 512];    // f1,f2,b1

__device__ __forceinline__ float fast_sigmoid(float x) {
    return 1.0f / (1.0f + __expf(-x));
}
__device__ __forceinline__ float fast_tanh(float x) {
    return 1.0f - 2.0f / (__expf(2.0f * x) + 1.0f);
}

__device__ __forceinline__ uint32_t smem_u32(const void* p) {
    uint32_t a;
    asm("{ .reg .u64 t; cvta.to.shared.u64 t, %1; cvt.u32.u64 %0, t; }"
        : "=r"(a) : "l"(p));
    return a;
}
__device__ __forceinline__ void ldmx4(uint32_t* r, uint32_t addr) {
    asm volatile(
        "ldmatrix.sync.aligned.m8n8.x4.shared.b16 {%0,%1,%2,%3}, [%4];"
        : "=r"(r[0]), "=r"(r[1]), "=r"(r[2]), "=r"(r[3]) : "r"(addr));
}
__device__ __forceinline__ void mma_bf16(float* c, const uint32_t* a,
                                         const uint32_t* b) {
    asm volatile(
        "mma.sync.aligned.m16n8k16.row.col.f32.bf16.bf16.f32 "
        "{%0,%1,%2,%3}, {%4,%5,%6,%7}, {%8,%9}, {%0,%1,%2,%3};"
        : "+f"(c[0]), "+f"(c[1]), "+f"(c[2]), "+f"(c[3])
        : "r"(a[0]), "r"(a[1]), "r"(a[2]), "r"(a[3]), "r"(b[0]), "r"(b[1]));
}

// ---------------------------------------------------------------------------
// bf16-split GEMM: C[M,256] = A[M,K] @ B[256,K]^T, 3-term hi/lo.
// CTA tile 128x128 (grid.y=2 covers N=256), BK=32, 8 warps of 32x64.
// Synchronous loads; smem stride 40 bf16 (80B): conflict-free ldmatrix
// (row offsets mod 128B = {0,80,32,112,64,16,96,48}). 40KB smem,
// launch_bounds(256,2) targets 2 CTAs/SM. Inner loop splits the 8 n8-tiles
// into two halves to keep live B-fragments at 16 regs.
// FUSE=0: write preact to Cz.  FUSE=1: read Cz as zpre, gate, write g_a/g_b.
// ---------------------------------------------------------------------------
#define GSTR 40
#define SOFF_AH 0
#define SOFF_AL (128 * GSTR)
#define SOFF_BH (2 * 128 * GSTR)
#define SOFF_BL (3 * 128 * GSTR)
#define GEMM_SMEM (4 * 128 * GSTR * 2)  // 40960 bytes

template <int FUSE>
__global__ __launch_bounds__(256, 2) void qrn_gemm_mma(
    const bf16* __restrict__ Ah, const bf16* __restrict__ Al, int lda, int K,
    const bf16* __restrict__ Bh, const bf16* __restrict__ Bl,
    float* __restrict__ Cz,                 // FUSE=0: out ; FUSE=1: zpre in
    const float* __restrict__ bz, const float* __restrict__ bh) {
    extern __shared__ bf16 sm[];
    const uint32_t sbase = smem_u32(sm);
    const int tid = threadIdx.x;
    const int wid = tid >> 5;
    const int lane = tid & 31;
    const int m0 = blockIdx.x * 128;
    const int n0 = blockIdx.y * 128;
    const int wm = (wid & 3) * 32;   // warp m-offset
    const int wn = (wid >> 2) * 64;  // warp n-offset

    float c[2][8][4];
#pragma unroll
    for (int mt = 0; mt < 2; mt++)
#pragma unroll
        for (int nt = 0; nt < 8; nt++)
#pragma unroll
            for (int j = 0; j < 4; j++) c[mt][nt][j] = 0.0f;

    const int la_row = (lane & 7) + ((lane >> 3) & 1) * 8;
    const int la_k = (lane >> 4) * 8;
    const int lb_row = (lane & 7) + (lane >> 4) * 8;
    const int lb_k = ((lane >> 3) & 1) * 8;

    for (int k0 = 0; k0 < K; k0 += 32) {
        __syncthreads();
        // load A/B chunks [128][32] hi+lo into padded smem
#pragma unroll
        for (int l = 0; l < 2; l++) {
            const int i = tid + l * 256;       // 512 x 16B per array
            const int r = i >> 2, c16 = i & 3; // 4 x 16B per 64B row
            const uint32_t so = (uint32_t)(r * GSTR + c16 * 8) * 2;
            const size_t ga = (size_t)(m0 + r) * lda + k0 + c16 * 8;
            const size_t gb = (size_t)(n0 + r) * K + k0 + c16 * 8;
            *(uint4*)((char*)sm + SOFF_AH * 2 + so) = *(const uint4*)(Ah + ga);
            *(uint4*)((char*)sm + SOFF_AL * 2 + so) = *(const uint4*)(Al + ga);
            *(uint4*)((char*)sm + SOFF_BH * 2 + so) = *(const uint4*)(Bh + gb);
            *(uint4*)((char*)sm + SOFF_BL * 2 + so) = *(const uint4*)(Bl + gb);
        }
        __syncthreads();

#pragma unroll
        for (int ks = 0; ks < 32; ks += 16) {
            uint32_t ah[2][4], al[2][4];
#pragma unroll
            for (int mt = 0; mt < 2; mt++) {
                const uint32_t ra =
                    sbase + ((wm + mt * 16 + la_row) * GSTR + ks + la_k) * 2;
                ldmx4(ah[mt], ra + SOFF_AH * 2);
                ldmx4(al[mt], ra + SOFF_AL * 2);
            }
            // two halves of 4 n8-tiles each: keeps live B frags at 16 regs
#pragma unroll
            for (int half = 0; half < 2; half++) {
                uint32_t bh2[4][2], bl2[4][2];
#pragma unroll
                for (int p = 0; p < 2; p++) {
                    const int ntp = half * 2 + p;
                    const uint32_t rb =
                        sbase + ((wn + ntp * 16 + lb_row) * GSTR + ks + lb_k) * 2;
                    uint32_t t[4];
                    ldmx4(t, rb + SOFF_BH * 2);
                    bh2[p * 2][0] = t[0]; bh2[p * 2][1] = t[1];
                    bh2[p * 2 + 1][0] = t[2]; bh2[p * 2 + 1][1] = t[3];
                    ldmx4(t, rb + SOFF_BL * 2);
                    bl2[p * 2][0] = t[0]; bl2[p * 2][1] = t[1];
                    bl2[p * 2 + 1][0] = t[2]; bl2[p * 2 + 1][1] = t[3];
                }
#pragma unroll
                for (int mt = 0; mt < 2; mt++)
#pragma unroll
                    for (int j = 0; j < 4; j++) {
                        float* acc = c[mt][half * 4 + j];
                        mma_bf16(acc, ah[mt], bh2[j]);
                        mma_bf16(acc, al[mt], bh2[j]);
                        mma_bf16(acc, ah[mt], bl2[j]);
                    }
            }
        }
    }

    // epilogue
#pragma unroll
    for (int mt = 0; mt < 2; mt++) {
#pragma unroll
        for (int nt = 0; nt < 8; nt++) {
            const int gr0 = m0 + wm + mt * 16 + (lane >> 2);
            const int gc = n0 + wn + nt * 8 + (lane & 3) * 2;
#pragma unroll
            for (int half = 0; half < 2; half++) {
                const int gr = gr0 + half * 8;
                const float v0 = c[mt][nt][half * 2];
                const float v1 = c[mt][nt][half * 2 + 1];
                if (FUSE == 0) {
                    *(float2*)&Cz[(size_t)gr * DD + gc] = make_float2(v0, v1);
                } else {
                    const float2 zp = *(const float2*)&Cz[(size_t)gr * DD + gc];
                    const float z0 = fast_sigmoid(zp.x + bz[gc]);
                    const float z1 = fast_sigmoid(zp.y + bz[gc + 1]);
                    const float t0 = fast_tanh(v0 + bh[gc]);
                    const float t1 = fast_tanh(v1 + bh[gc + 1]);
                    *(float2*)&g_a[(size_t)gr * DD + gc] =
                        make_float2(1.0f - z0, 1.0f - z1);
                    *(float2*)&g_b[(size_t)gr * DD + gc] =
                        make_float2(z0 * t0, z1 * t1);
                }
            }
        }
    }
}

// ---------------------------------------------------------------------------
// Prolog kernels (merged so the first GEMM is launch #4, the ncu window)
// ---------------------------------------------------------------------------
// Launch 1: story fp32 -> xcat cols [0,256) bf16 hi/lo
__global__ void split_x_kernel(const float* __restrict__ story) {
    const int idx = blockIdx.x * blockDim.x + threadIdx.x;
    const int t = idx >> 8, d = idx & 255;
    const float v = story[idx];
    const bf16 h = __float2bfloat16(v);
    g_xcat_h[(size_t)t * 512 + d] = h;
    g_xcat_l[(size_t)t * 512 + d] = __float2bfloat16(v - __bfloat162float(h));
}

// Launch 2: both layer-0 folds for both directions.
// grid (264, 2): x<256 -> fold_wz row x; x>=256 -> fold_ch block (x-256).
__global__ void fold_all_kernel(const float* __restrict__ question,
                                const float* __restrict__ Wzf,
                                const float* __restrict__ Whf,
                                const float* __restrict__ bhf,
                                const float* __restrict__ Wzb,
                                const float* __restrict__ Whb,
                                const float* __restrict__ bhb) {
    const int dir = blockIdx.y;
    const float* Wz = dir ? Wzb : Wzf;
    const float* Whbot = (dir ? Whb : Whf) + DD * DD;
    const float* bh = dir ? bhb : bhf;
    float* Wzp = dir ? g_Wz0b : g_Wz0f;
    float* ch = dir ? g_ch0b : g_ch0f;

    if (blockIdx.x < 256) {
        const int k = blockIdx.x, n = threadIdx.x;
        Wzp[k * DD + n] = question[k] * Wz[k * DD + n];
    } else {
        __shared__ float red[8][32];
        const int nl = threadIdx.x & 31;
        const int kp = threadIdx.x >> 5;
        const int n = (blockIdx.x - 256) * 32 + nl;
        float s = 0.0f;
        for (int k = kp; k < DD; k += 8)
            s = fmaf(question[k], Whbot[k * DD + n], s);
        red[kp][nl] = s;
        __syncthreads();
        if (kp == 0) {
            float t = bh[n];
#pragma unroll
            for (int j = 0; j < 8; j++) t += red[j][nl];
            ch[n] = t;
        }
    }
}

// Launch 3: all 10 weight transpose+split conversions. grid (512, 10).
__global__ void conv_all_kernel(const float* __restrict__ Wzf,
                                const float* __restrict__ Whf,
                                const float* __restrict__ Wzb,
                                const float* __restrict__ Whb) {
    const int task = blockIdx.y;
    const int k = blockIdx.x;
    const int n = threadIdx.x;
    const float* src;
    bf16 *oh, *ol;
    int K = 256;
    switch (task) {
        case 0: src = g_Wz0f; oh = g_Wz0fT_h; ol = g_Wz0fT_l; break;
        case 1: src = g_Wz0b; oh = g_Wz0bT_h; ol = g_Wz0bT_l; break;
        case 2: src = Whf; oh = g_Wt0fT_h; ol = g_Wt0fT_l; break;
        case 3: src = Whb; oh = g_Wt0bT_h; ol = g_Wt0bT_l; break;
        case 4: src = Wzf + 1 * DD * DD; oh = g_WzT_h; ol = g_WzT_l; break;
        case 5: src = Wzf + 2 * DD * DD; oh = g_WzT_h + DD * DD;
                ol = g_WzT_l + DD * DD; break;
        case 6: src = Wzb + 1 * DD * DD; oh = g_WzT_h + 2 * DD * DD;
                ol = g_WzT_l + 2 * DD * DD; break;
        case 7: src = Whf + 1 * 2 * DD * DD; oh = g_WhT_h; ol = g_WhT_l;
                K = 512; break;
        case 8: src = Whf + 2 * 2 * DD * DD; oh = g_WhT_h + DD * 512;
                ol = g_WhT_l + DD * 512; K = 512; break;
        default: src = Whb + 1 * 2 * DD * DD; oh = g_WhT_h + 2 * DD * 512;
                 ol = g_WhT_l + 2 * DD * 512; K = 512; break;
    }
    if (k >= K) return;
    const float v = src[k * DD + n];
    const bf16 h = __float2bfloat16(v);
    oh[(size_t)n * K + k] = h;
    ol[(size_t)n * K + k] = __float2bfloat16(v - __bfloat162float(h));
}

// ---------------------------------------------------------------------------
// Scans (3-pass chunked linear recurrence; channel = threadIdx.x)
// ---------------------------------------------------------------------------
template <int REV>
__global__ void scan1_kernel() {
    const int c = blockIdx.x, d = threadIdx.x;
    float Ar = 1.0f, Br = 0.0f;
    const int base = c * CH;
#pragma unroll 4
    for (int i = 0; i < CH; i++) {
        const int t = base + (REV ? (CH - 1 - i) : i);
        const float a = g_a[(size_t)t * DD + d];
        const float b = g_b[(size_t)t * DD + d];
        Br = fmaf(a, Br, b);
        Ar *= a;
    }
    g_Aagg[c * DD + d] = Ar;
    g_Bagg[c * DD + d] = Br;
}

#define S2_BATCH 16
template <int REV>
__global__ void scan2_kernel() {
    const int d = blockIdx.x * 32 + threadIdx.x;
    float h = 0.0f;
    for (int ci0 = 0; ci0 < NC; ci0 += S2_BATCH) {
        float A[S2_BATCH], B[S2_BATCH];
#pragma unroll
        for (int j = 0; j < S2_BATCH; j++) {
            const int c = REV ? (NC - 1 - (ci0 + j)) : (ci0 + j);
            A[j] = g_Aagg[c * DD + d];
            B[j] = g_Bagg[c * DD + d];
        }
#pragma unroll
        for (int j = 0; j < S2_BATCH; j++) {
            const int c = REV ? (NC - 1 - (ci0 + j)) : (ci0 + j);
            g_pref[c * DD + d] = h;
            h = fmaf(A[j], h, B[j]);
        }
    }
}

__global__ void scan3_fwd_kernel() {
    const int c = blockIdx.x, d = threadIdx.x;
    float h = g_pref[c * DD + d];
    const int base = c * CH;
#pragma unroll 4
    for (int i = 0; i < CH; i++) {
        const int t = base + i;
        h = fmaf(g_a[(size_t)t * DD + d], h, g_b[(size_t)t * DD + d]);
        g_hf[(size_t)t * DD + d] = h;
    }
}

// Backward scan fused with next-layer operand prep:
//   q = h_bwd + h_fwd -> xcat[:,256+d] hi/lo ; xq = story*q -> xq hi/lo
__global__ void scan3_bwd_conv_kernel(const float* __restrict__ story) {
    const int c = blockIdx.x, d = threadIdx.x;
    float h = g_pref[c * DD + d];
    const int base = c * CH;
#pragma unroll 4
    for (int i = CH - 1; i >= 0; i--) {
        const int t = base + i;
        h = fmaf(g_a[(size_t)t * DD + d], h, g_b[(size_t)t * DD + d]);
        const float q = h + g_hf[(size_t)t * DD + d];
        const bf16 qh = __float2bfloat16(q);
        g_xcat_h[(size_t)t * 512 + 256 + d] = qh;
        g_xcat_l[(size_t)t * 512 + 256 + d] =
            __float2bfloat16(q - __bfloat162float(qh));
        const float p = story[(size_t)t * DD + d] * q;
        const bf16 ph = __float2bfloat16(p);
        g_xq_h[(size_t)t * DD + d] = ph;
        g_xq_l[(size_t)t * DD + d] =
            __float2bfloat16(p - __bfloat162float(ph));
    }
}

__global__ void final_kernel(float* __restrict__ out) {
    const int d = blockIdx.x * 32 + threadIdx.x;
    float h = 0.0f;
    for (int c0 = 0; c0 < NC; c0 += S2_BATCH) {
        float A[S2_BATCH], B[S2_BATCH];
#pragma unroll
        for (int j = 0; j < S2_BATCH; j++) {
            A[j] = g_Aagg[(c0 + j) * DD + d];
            B[j] = g_Bagg[(c0 + j) * DD + d];
        }
#pragma unroll
        for (int j = 0; j < S2_BATCH; j++) h = fmaf(A[j], h, B[j]);
    }
    out[d] = h;
}

// ---------------------------------------------------------------------------
extern "C" void kernel_launch(void* const* d_in, const int* in_sizes, int n_in,
                              void* d_out, int out_size) {
    const float* story = (const float*)d_in[0];
    const float* question = (const float*)d_in[1];
    const float* Wzf = (const float*)d_in[2];
    const float* bzf = (const float*)d_in[3];
    const float* Whf = (const float*)d_in[4];
    const float* bhf = (const float*)d_in[5];
    const float* Wzb = (const float*)d_in[6];
    const float* bzb = (const float*)d_in[7];
    const float* Whb = (const float*)d_in[8];
    const float* bhb = (const float*)d_in[9];
    float* out = (float*)d_out;

    cudaFuncSetAttribute(qrn_gemm_mma<0>,
                         cudaFuncAttributeMaxDynamicSharedMemorySize, GEMM_SMEM);
    cudaFuncSetAttribute(qrn_gemm_mma<1>,
                         cudaFuncAttributeMaxDynamicSharedMemorySize, GEMM_SMEM);

#define SYM(v, s) void* v; cudaGetSymbolAddress(&v, s)
    SYM(pch0f, g_ch0f); SYM(pch0b, g_ch0b);
    SYM(pXh, g_xcat_h); SYM(pXl, g_xcat_l);
    SYM(pQh, g_xq_h);   SYM(pQl, g_xq_l);
    SYM(pZp, g_zpre);
    SYM(pWz0fTh, g_Wz0fT_h); SYM(pWz0fTl, g_Wz0fT_l);
    SYM(pWz0bTh, g_Wz0bT_h); SYM(pWz0bTl, g_Wz0bT_l);
    SYM(pWt0fTh, g_Wt0fT_h); SYM(pWt0fTl, g_Wt0fT_l);
    SYM(pWt0bTh, g_Wt0bT_h); SYM(pWt0bTl, g_Wt0bT_l);
    SYM(pWzTh, g_WzT_h); SYM(pWzTl, g_WzT_l);
    SYM(pWhTh, g_WhT_h); SYM(pWhTl, g_WhT_l);
#undef SYM
#define BF(p) ((bf16*)(p))
#define F32(p) ((float*)(p))

    // ---- prolog: exactly 3 launches, so launch #4 = first GEMM (ncu slot) ----
    split_x_kernel<<<TT * DD / 256, 256>>>(story);                    // 1
    fold_all_kernel<<<dim3(264, 2), 256>>>(question, Wzf, Whf, bhf,   // 2
                                           Wzb, Whb, bhb);
    conv_all_kernel<<<dim3(512, 10), 256>>>(Wzf, Whf, Wzb, Whb);      // 3

    const dim3 gg(TT / 128, 2);

    // ---- layer 0 fwd (A = x slice of xcat, lda=512, K=256) ----
    qrn_gemm_mma<0><<<gg, 256, GEMM_SMEM>>>(BF(pXh), BF(pXl), 512, 256,  // 4
                                            BF(pWz0fTh), BF(pWz0fTl),
                                            F32(pZp), nullptr, nullptr);
    qrn_gemm_mma<1><<<gg, 256, GEMM_SMEM>>>(BF(pXh), BF(pXl), 512, 256,
                                            BF(pWt0fTh), BF(pWt0fTl),
                                            F32(pZp), bzf, F32(pch0f));
    scan1_kernel<0><<<NC, DD>>>();
    scan2_kernel<0><<<8, 32>>>();
    scan3_fwd_kernel<<<NC, DD>>>();
    // ---- layer 0 bwd ----
    qrn_gemm_mma<0><<<gg, 256, GEMM_SMEM>>>(BF(pXh), BF(pXl), 512, 256,
                                            BF(pWz0bTh), BF(pWz0bTl),
                                            F32(pZp), nullptr, nullptr);
    qrn_gemm_mma<1><<<gg, 256, GEMM_SMEM>>>(BF(pXh), BF(pXl), 512, 256,
                                            BF(pWt0bTh), BF(pWt0bTl),
                                            F32(pZp), bzb, F32(pch0b));
    scan1_kernel<1><<<NC, DD>>>();
    scan2_kernel<1><<<8, 32>>>();
    scan3_bwd_conv_kernel<<<NC, DD>>>(story);  // q, xq hi/lo for layer 1

    // ---- layer 1 fwd ----
    qrn_gemm_mma<0><<<gg, 256, GEMM_SMEM>>>(
        BF(pQh), BF(pQl), 256, 256,
        BF(pWzTh) + 0 * DD * DD, BF(pWzTl) + 0 * DD * DD,
        F32(pZp), nullptr, nullptr);
    qrn_gemm_mma<1><<<gg, 256, GEMM_SMEM>>>(
        BF(pXh), BF(pXl), 512, 512,
        BF(pWhTh) + 0 * DD * 512, BF(pWhTl) + 0 * DD * 512,
        F32(pZp), bzf + DD, bhf + DD);
    scan1_kernel<0><<<NC, DD>>>();
    scan2_kernel<0><<<8, 32>>>();
    scan3_fwd_kernel<<<NC, DD>>>();
    // ---- layer 1 bwd ----
    qrn_gemm_mma<0><<<gg, 256, GEMM_SMEM>>>(
        BF(pQh), BF(pQl), 256, 256,
        BF(pWzTh) + 2 * DD * DD, BF(pWzTl) + 2 * DD * DD,
        F32(pZp), nullptr, nullptr);
    qrn_gemm_mma<1><<<gg, 256, GEMM_SMEM>>>(
        BF(pXh), BF(pXl), 512, 512,
        BF(pWhTh) + 2 * DD * 512, BF(pWhTl) + 2 * DD * 512,
        F32(pZp), bzb + DD, bhb + DD);
    scan1_kernel<1><<<NC, DD>>>();
    scan2_kernel<1><<<8, 32>>>();
    scan3_bwd_conv_kernel<<<NC, DD>>>(story);  // q, xq for layer 2

    // ---- layer 2 fwd (only h_fwd[T-1] needed) ----
    qrn_gemm_mma<0><<<gg, 256, GEMM_SMEM>>>(
        BF(pQh), BF(pQl), 256, 256,
        BF(pWzTh) + 1 * DD * DD, BF(pWzTl) + 1 * DD * DD,
        F32(pZp), nullptr, nullptr);
    qrn_gemm_mma<1><<<gg, 256, GEMM_SMEM>>>(
        BF(pXh), BF(pXl), 512, 512,
        BF(pWhTh) + 1 * DD * 512, BF(pWhTl) + 1 * DD * 512,
        F32(pZp), bzf + 2 * DD, bhf + 2 * DD);
    scan1_kernel<0><<<NC, DD>>>();
    final_kernel<<<8, 32>>>(out);
}

// round 16
// speedup vs baseline: 1.2614x; 1.1345x over previous
#include <cuda_runtime.h>
#include <cuda_bf16.h>
#include <cstdint>

// ---------------------------------------------------------------------------
// QRN: 3-layer bidirectional quasi-RNN, T=65536, D=256.
// mma.sync (HMMA bf16, fp32 accum) — tcgen05 unavailable (plain sm_103 PTX
// target, verified R9). 3-term bf16 split (hi*hi + hi*lo + lo*hi) gives
// fp32-grade accuracy. 2-stage cp.async GEMM pipeline with forced
// __launch_bounds__(256,2) (R11's pipeline failed only because regs>128 ->
// 1 CTA/SM; R12 proved 128 regs holds). Gate fused into h-GEMM epilogue.
// Layer-0: q constant -> folded weights. Prolog = 3 launches so ncu's
// launch-#4 window captures the z-GEMM.
// Output: h_fwd[T-1] of last layer (layer-2 backward pass is dead code).
// ---------------------------------------------------------------------------

#define TT 65536
#define DD 256
#define CH 256
#define NC (TT / CH)

typedef __nv_bfloat16 bf16;

// ----- scratch (device globals; no runtime allocation allowed) -----
__device__ float g_a[TT * DD];
__device__ float g_b[TT * DD];
__device__ float g_hf[TT * DD];
__device__ float g_zpre[TT * DD];
__device__ float g_Aagg[NC * DD];
__device__ float g_Bagg[NC * DD];
__device__ float g_pref[NC * DD];
__device__ float g_Wz0f[DD * DD];
__device__ float g_ch0f[DD];
__device__ float g_Wz0b[DD * DD];
__device__ float g_ch0b[DD];

// bf16 split operands
__device__ bf16 g_xcat_h[TT * 512];  // [t][0:256]=x, [256:512]=q (per layer)
__device__ bf16 g_xcat_l[TT * 512];
__device__ bf16 g_xq_h[TT * DD];     // x*q (layers >= 1)
__device__ bf16 g_xq_l[TT * DD];

// transposed K-major bf16 weights: [n][k]
__device__ bf16 g_Wz0fT_h[DD * DD], g_Wz0fT_l[DD * DD];
__device__ bf16 g_Wz0bT_h[DD * DD], g_Wz0bT_l[DD * DD];
__device__ bf16 g_Wt0fT_h[DD * DD], g_Wt0fT_l[DD * DD];   // layer-0 Wh top
__device__ bf16 g_Wt0bT_h[DD * DD], g_Wt0bT_l[DD * DD];
__device__ bf16 g_WzT_h[3 * DD * DD], g_WzT_l[3 * DD * DD];      // f1,f2,b1
__device__ bf16 g_WhT_h[3 * DD * 512], g_WhT_l[3 * DD * 512];    // f1,f2,b1

__device__ __forceinline__ float fast_sigmoid(float x) {
    return 1.0f / (1.0f + __expf(-x));
}
__device__ __forceinline__ float fast_tanh(float x) {
    return 1.0f - 2.0f / (__expf(2.0f * x) + 1.0f);
}

__device__ __forceinline__ uint32_t smem_u32(const void* p) {
    uint32_t a;
    asm("{ .reg .u64 t; cvta.to.shared.u64 t, %1; cvt.u32.u64 %0, t; }"
        : "=r"(a) : "l"(p));
    return a;
}
__device__ __forceinline__ void ldmx4(uint32_t* r, uint32_t addr) {
    asm volatile(
        "ldmatrix.sync.aligned.m8n8.x4.shared.b16 {%0,%1,%2,%3}, [%4];"
        : "=r"(r[0]), "=r"(r[1]), "=r"(r[2]), "=r"(r[3]) : "r"(addr));
}
__device__ __forceinline__ void mma_bf16(float* c, const uint32_t* a,
                                         const uint32_t* b) {
    asm volatile(
        "mma.sync.aligned.m16n8k16.row.col.f32.bf16.bf16.f32 "
        "{%0,%1,%2,%3}, {%4,%5,%6,%7}, {%8,%9}, {%0,%1,%2,%3};"
        : "+f"(c[0]), "+f"(c[1]), "+f"(c[2]), "+f"(c[3])
        : "r"(a[0]), "r"(a[1]), "r"(a[2]), "r"(a[3]), "r"(b[0]), "r"(b[1]));
}
#define CP_ASYNC(dst, src) \
    asm volatile("cp.async.cg.shared.global [%0], [%1], 16;" \
                 :: "r"(dst), "l"(src))
#define CP_COMMIT() asm volatile("cp.async.commit_group;" ::: "memory")
#define CP_WAIT(n) asm volatile("cp.async.wait_group %0;" :: "n"(n) : "memory")

// ---------------------------------------------------------------------------
// bf16-split GEMM: C[M,256] = A[M,K] @ B[256,K]^T, 3-term hi/lo.
// CTA tile 128x128 (grid.y=2 covers N=256), BK=32, 8 warps of 32x64.
// 2-stage cp.async pipeline; smem stride 40 bf16 (80B): conflict-free
// ldmatrix (row offsets mod 128B = {0,80,32,112,64,16,96,48}).
// 2 x 40KB stages = 80KB; launch_bounds(256,2) -> 128 regs, 2 CTAs/SM
// (160KB smem of 228KB, full 64K-reg RF).
// FUSE=0: write preact to Cz.  FUSE=1: read Cz as zpre, gate, write g_a/g_b.
// ---------------------------------------------------------------------------
#define GSTR 40
#define SOFF_AH 0
#define SOFF_AL (128 * GSTR)
#define SOFF_BH (2 * 128 * GSTR)
#define SOFF_BL (3 * 128 * GSTR)
#define STAGE_BF16 (4 * 128 * GSTR)             // 20480 bf16 = 40960 B
#define GEMM_SMEM (2 * STAGE_BF16 * 2)          // 81920 bytes

__device__ __forceinline__ void load_chunk_async(
    uint32_t sstage, const bf16* __restrict__ Ah, const bf16* __restrict__ Al,
    int lda, const bf16* __restrict__ Bh, const bf16* __restrict__ Bl, int ldb,
    int m0, int n0, int k0, int tid) {
#pragma unroll
    for (int l = 0; l < 2; l++) {
        const int i = tid + l * 256;       // 512 x 16B per array
        const int r = i >> 2, c16 = i & 3; // 4 x 16B per 64B row
        const uint32_t so = (uint32_t)(r * GSTR + c16 * 8) * 2;
        const size_t ga = (size_t)(m0 + r) * lda + k0 + c16 * 8;
        const size_t gb = (size_t)(n0 + r) * ldb + k0 + c16 * 8;
        CP_ASYNC(sstage + SOFF_AH * 2 + so, Ah + ga);
        CP_ASYNC(sstage + SOFF_AL * 2 + so, Al + ga);
        CP_ASYNC(sstage + SOFF_BH * 2 + so, Bh + gb);
        CP_ASYNC(sstage + SOFF_BL * 2 + so, Bl + gb);
    }
}

template <int FUSE>
__global__ __launch_bounds__(256, 2) void qrn_gemm_mma(
    const bf16* __restrict__ Ah, const bf16* __restrict__ Al, int lda, int K,
    const bf16* __restrict__ Bh, const bf16* __restrict__ Bl,
    float* __restrict__ Cz,                 // FUSE=0: out ; FUSE=1: zpre in
    const float* __restrict__ bz, const float* __restrict__ bh) {
    extern __shared__ bf16 sm[];
    const uint32_t sbase = smem_u32(sm);
    const int tid = threadIdx.x;
    const int wid = tid >> 5;
    const int lane = tid & 31;
    const int m0 = blockIdx.x * 128;
    const int n0 = blockIdx.y * 128;
    const int wm = (wid & 3) * 32;   // warp m-offset
    const int wn = (wid >> 2) * 64;  // warp n-offset

    float c[2][8][4];
#pragma unroll
    for (int mt = 0; mt < 2; mt++)
#pragma unroll
        for (int nt = 0; nt < 8; nt++)
#pragma unroll
            for (int j = 0; j < 4; j++) c[mt][nt][j] = 0.0f;

    const int la_row = (lane & 7) + ((lane >> 3) & 1) * 8;
    const int la_k = (lane >> 4) * 8;
    const int lb_row = (lane & 7) + (lane >> 4) * 8;
    const int lb_k = ((lane >> 3) & 1) * 8;

    const int nch = K >> 5;
    // prologue: prefetch chunk 0 into stage 0
    load_chunk_async(sbase, Ah, Al, lda, Bh, Bl, K, m0, n0, 0, tid);
    CP_COMMIT();

    for (int ch = 0; ch < nch; ch++) {
        if (ch + 1 < nch) {
            load_chunk_async(sbase + ((ch + 1) & 1) * STAGE_BF16 * 2, Ah, Al,
                             lda, Bh, Bl, K, m0, n0, (ch + 1) * 32, tid);
            CP_COMMIT();
            CP_WAIT(1);   // chunk ch resident
        } else {
            CP_WAIT(0);
        }
        __syncthreads();  // chunk-ch smem visible to all warps

        const uint32_t st = sbase + (ch & 1) * STAGE_BF16 * 2;
#pragma unroll
        for (int ks = 0; ks < 32; ks += 16) {
            uint32_t ah[2][4], al[2][4];
#pragma unroll
            for (int mt = 0; mt < 2; mt++) {
                const uint32_t ra =
                    st + ((wm + mt * 16 + la_row) * GSTR + ks + la_k) * 2;
                ldmx4(ah[mt], ra + SOFF_AH * 2);
                ldmx4(al[mt], ra + SOFF_AL * 2);
            }
            // two halves of 4 n8-tiles each: keeps live B frags at 16 regs
#pragma unroll
            for (int half = 0; half < 2; half++) {
                uint32_t bh2[4][2], bl2[4][2];
#pragma unroll
                for (int p = 0; p < 2; p++) {
                    const int ntp = half * 2 + p;
                    const uint32_t rb =
                        st + ((wn + ntp * 16 + lb_row) * GSTR + ks + lb_k) * 2;
                    uint32_t t[4];
                    ldmx4(t, rb + SOFF_BH * 2);
                    bh2[p * 2][0] = t[0]; bh2[p * 2][1] = t[1];
                    bh2[p * 2 + 1][0] = t[2]; bh2[p * 2 + 1][1] = t[3];
                    ldmx4(t, rb + SOFF_BL * 2);
                    bl2[p * 2][0] = t[0]; bl2[p * 2][1] = t[1];
                    bl2[p * 2 + 1][0] = t[2]; bl2[p * 2 + 1][1] = t[3];
                }
#pragma unroll
                for (int mt = 0; mt < 2; mt++)
#pragma unroll
                    for (int j = 0; j < 4; j++) {
                        float* acc = c[mt][half * 4 + j];
                        mma_bf16(acc, ah[mt], bh2[j]);
                        mma_bf16(acc, al[mt], bh2[j]);
                        mma_bf16(acc, ah[mt], bl2[j]);
                    }
            }
        }
        __syncthreads();  // all warps done with stage ch&1 before re-prefetch
    }

    // epilogue
#pragma unroll
    for (int mt = 0; mt < 2; mt++) {
#pragma unroll
        for (int nt = 0; nt < 8; nt++) {
            const int gr0 = m0 + wm + mt * 16 + (lane >> 2);
            const int gc = n0 + wn + nt * 8 + (lane & 3) * 2;
#pragma unroll
            for (int half = 0; half < 2; half++) {
                const int gr = gr0 + half * 8;
                const float v0 = c[mt][nt][half * 2];
                const float v1 = c[mt][nt][half * 2 + 1];
                if (FUSE == 0) {
                    *(float2*)&Cz[(size_t)gr * DD + gc] = make_float2(v0, v1);
                } else {
                    const float2 zp = *(const float2*)&Cz[(size_t)gr * DD + gc];
                    const float z0 = fast_sigmoid(zp.x + bz[gc]);
                    const float z1 = fast_sigmoid(zp.y + bz[gc + 1]);
                    const float t0 = fast_tanh(v0 + bh[gc]);
                    const float t1 = fast_tanh(v1 + bh[gc + 1]);
                    *(float2*)&g_a[(size_t)gr * DD + gc] =
                        make_float2(1.0f - z0, 1.0f - z1);
                    *(float2*)&g_b[(size_t)gr * DD + gc] =
                        make_float2(z0 * t0, z1 * t1);
                }
            }
        }
    }
}

// ---------------------------------------------------------------------------
// Prolog kernels (merged so the first GEMM is launch #4, the ncu window)
// ---------------------------------------------------------------------------
__global__ void split_x_kernel(const float* __restrict__ story) {
    const int idx = blockIdx.x * blockDim.x + threadIdx.x;
    const int t = idx >> 8, d = idx & 255;
    const float v = story[idx];
    const bf16 h = __float2bfloat16(v);
    g_xcat_h[(size_t)t * 512 + d] = h;
    g_xcat_l[(size_t)t * 512 + d] = __float2bfloat16(v - __bfloat162float(h));
}

// grid (264, 2): x<256 -> fold_wz row x; x>=256 -> fold_ch block (x-256).
__global__ void fold_all_kernel(const float* __restrict__ question,
                                const float* __restrict__ Wzf,
                                const float* __restrict__ Whf,
                                const float* __restrict__ bhf,
                                const float* __restrict__ Wzb,
                                const float* __restrict__ Whb,
                                const float* __restrict__ bhb) {
    const int dir = blockIdx.y;
    const float* Wz = dir ? Wzb : Wzf;
    const float* Whbot = (dir ? Whb : Whf) + DD * DD;
    const float* bh = dir ? bhb : bhf;
    float* Wzp = dir ? g_Wz0b : g_Wz0f;
    float* ch = dir ? g_ch0b : g_ch0f;

    if (blockIdx.x < 256) {
        const int k = blockIdx.x, n = threadIdx.x;
        Wzp[k * DD + n] = question[k] * Wz[k * DD + n];
    } else {
        __shared__ float red[8][32];
        const int nl = threadIdx.x & 31;
        const int kp = threadIdx.x >> 5;
        const int n = (blockIdx.x - 256) * 32 + nl;
        float s = 0.0f;
        for (int k = kp; k < DD; k += 8)
            s = fmaf(question[k], Whbot[k * DD + n], s);
        red[kp][nl] = s;
        __syncthreads();
        if (kp == 0) {
            float t = bh[n];
#pragma unroll
            for (int j = 0; j < 8; j++) t += red[j][nl];
            ch[n] = t;
        }
    }
}

// all 10 weight transpose+split conversions. grid (512, 10).
__global__ void conv_all_kernel(const float* __restrict__ Wzf,
                                const float* __restrict__ Whf,
                                const float* __restrict__ Wzb,
                                const float* __restrict__ Whb) {
    const int task = blockIdx.y;
    const int k = blockIdx.x;
    const int n = threadIdx.x;
    const float* src;
    bf16 *oh, *ol;
    int K = 256;
    switch (task) {
        case 0: src = g_Wz0f; oh = g_Wz0fT_h; ol = g_Wz0fT_l; break;
        case 1: src = g_Wz0b; oh = g_Wz0bT_h; ol = g_Wz0bT_l; break;
        case 2: src = Whf; oh = g_Wt0fT_h; ol = g_Wt0fT_l; break;
        case 3: src = Whb; oh = g_Wt0bT_h; ol = g_Wt0bT_l; break;
        case 4: src = Wzf + 1 * DD * DD; oh = g_WzT_h; ol = g_WzT_l; break;
        case 5: src = Wzf + 2 * DD * DD; oh = g_WzT_h + DD * DD;
                ol = g_WzT_l + DD * DD; break;
        case 6: src = Wzb + 1 * DD * DD; oh = g_WzT_h + 2 * DD * DD;
                ol = g_WzT_l + 2 * DD * DD; break;
        case 7: src = Whf + 1 * 2 * DD * DD; oh = g_WhT_h; ol = g_WhT_l;
                K = 512; break;
        case 8: src = Whf + 2 * 2 * DD * DD; oh = g_WhT_h + DD * 512;
                ol = g_WhT_l + DD * 512; K = 512; break;
        default: src = Whb + 1 * 2 * DD * DD; oh = g_WhT_h + 2 * DD * 512;
                 ol = g_WhT_l + 2 * DD * 512; K = 512; break;
    }
    if (k >= K) return;
    const float v = src[k * DD + n];
    const bf16 h = __float2bfloat16(v);
    oh[(size_t)n * K + k] = h;
    ol[(size_t)n * K + k] = __float2bfloat16(v - __bfloat162float(h));
}

// ---------------------------------------------------------------------------
// Scans (3-pass chunked linear recurrence; channel = threadIdx.x)
// ---------------------------------------------------------------------------
template <int REV>
__global__ void scan1_kernel() {
    const int c = blockIdx.x, d = threadIdx.x;
    float Ar = 1.0f, Br = 0.0f;
    const int base = c * CH;
#pragma unroll 8
    for (int i = 0; i < CH; i++) {
        const int t = base + (REV ? (CH - 1 - i) : i);
        const float a = g_a[(size_t)t * DD + d];
        const float b = g_b[(size_t)t * DD + d];
        Br = fmaf(a, Br, b);
        Ar *= a;
    }
    g_Aagg[c * DD + d] = Ar;
    g_Bagg[c * DD + d] = Br;
}

#define S2_BATCH 16
template <int REV>
__global__ void scan2_kernel() {
    const int d = blockIdx.x * 32 + threadIdx.x;
    float h = 0.0f;
    for (int ci0 = 0; ci0 < NC; ci0 += S2_BATCH) {
        float A[S2_BATCH], B[S2_BATCH];
#pragma unroll
        for (int j = 0; j < S2_BATCH; j++) {
            const int c = REV ? (NC - 1 - (ci0 + j)) : (ci0 + j);
            A[j] = g_Aagg[c * DD + d];
            B[j] = g_Bagg[c * DD + d];
        }
#pragma unroll
        for (int j = 0; j < S2_BATCH; j++) {
            const int c = REV ? (NC - 1 - (ci0 + j)) : (ci0 + j);
            g_pref[c * DD + d] = h;
            h = fmaf(A[j], h, B[j]);
        }
    }
}

__global__ void scan3_fwd_kernel() {
    const int c = blockIdx.x, d = threadIdx.x;
    float h = g_pref[c * DD + d];
    const int base = c * CH;
#pragma unroll 8
    for (int i = 0; i < CH; i++) {
        const int t = base + i;
        h = fmaf(g_a[(size_t)t * DD + d], h, g_b[(size_t)t * DD + d]);
        g_hf[(size_t)t * DD + d] = h;
    }
}

// Backward scan fused with next-layer operand prep:
//   q = h_bwd + h_fwd -> xcat[:,256+d] hi/lo ; xq = story*q -> xq hi/lo
__global__ void scan3_bwd_conv_kernel(const float* __restrict__ story) {
    const int c = blockIdx.x, d = threadIdx.x;
    float h = g_pref[c * DD + d];
    const int base = c * CH;
#pragma unroll 8
    for (int i = CH - 1; i >= 0; i--) {
        const int t = base + i;
        h = fmaf(g_a[(size_t)t * DD + d], h, g_b[(size_t)t * DD + d]);
        const float q = h + g_hf[(size_t)t * DD + d];
        const bf16 qh = __float2bfloat16(q);
        g_xcat_h[(size_t)t * 512 + 256 + d] = qh;
        g_xcat_l[(size_t)t * 512 + 256 + d] =
            __float2bfloat16(q - __bfloat162float(qh));
        const float p = story[(size_t)t * DD + d] * q;
        const bf16 ph = __float2bfloat16(p);
        g_xq_h[(size_t)t * DD + d] = ph;
        g_xq_l[(size_t)t * DD + d] =
            __float2bfloat16(p - __bfloat162float(ph));
    }
}

__global__ void final_kernel(float* __restrict__ out) {
    const int d = blockIdx.x * 32 + threadIdx.x;
    float h = 0.0f;
    for (int c0 = 0; c0 < NC; c0 += S2_BATCH) {
        float A[S2_BATCH], B[S2_BATCH];
#pragma unroll
        for (int j = 0; j < S2_BATCH; j++) {
            A[j] = g_Aagg[(c0 + j) * DD + d];
            B[j] = g_Bagg[(c0 + j) * DD + d];
        }
#pragma unroll
        for (int j = 0; j < S2_BATCH; j++) h = fmaf(A[j], h, B[j]);
    }
    out[d] = h;
}

// ---------------------------------------------------------------------------
extern "C" void kernel_launch(void* const* d_in, const int* in_sizes, int n_in,
                              void* d_out, int out_size) {
    const float* story = (const float*)d_in[0];
    const float* question = (const float*)d_in[1];
    const float* Wzf = (const float*)d_in[2];
    const float* bzf = (const float*)d_in[3];
    const float* Whf = (const float*)d_in[4];
    const float* bhf = (const float*)d_in[5];
    const float* Wzb = (const float*)d_in[6];
    const float* bzb = (const float*)d_in[7];
    const float* Whb = (const float*)d_in[8];
    const float* bhb = (const float*)d_in[9];
    float* out = (float*)d_out;

    cudaFuncSetAttribute(qrn_gemm_mma<0>,
                         cudaFuncAttributeMaxDynamicSharedMemorySize, GEMM_SMEM);
    cudaFuncSetAttribute(qrn_gemm_mma<1>,
                         cudaFuncAttributeMaxDynamicSharedMemorySize, GEMM_SMEM);

#define SYM(v, s) void* v; cudaGetSymbolAddress(&v, s)
    SYM(pch0f, g_ch0f); SYM(pch0b, g_ch0b);
    SYM(pXh, g_xcat_h); SYM(pXl, g_xcat_l);
    SYM(pQh, g_xq_h);   SYM(pQl, g_xq_l);
    SYM(pZp, g_zpre);
    SYM(pWz0fTh, g_Wz0fT_h); SYM(pWz0fTl, g_Wz0fT_l);
    SYM(pWz0bTh, g_Wz0bT_h); SYM(pWz0bTl, g_Wz0bT_l);
    SYM(pWt0fTh, g_Wt0fT_h); SYM(pWt0fTl, g_Wt0fT_l);
    SYM(pWt0bTh, g_Wt0bT_h); SYM(pWt0bTl, g_Wt0bT_l);
    SYM(pWzTh, g_WzT_h); SYM(pWzTl, g_WzT_l);
    SYM(pWhTh, g_WhT_h); SYM(pWhTl, g_WhT_l);
#undef SYM
#define BF(p) ((bf16*)(p))
#define F32(p) ((float*)(p))

    // ---- prolog: exactly 3 launches, so launch #4 = first GEMM (ncu slot) ----
    split_x_kernel<<<TT * DD / 256, 256>>>(story);                    // 1
    fold_all_kernel<<<dim3(264, 2), 256>>>(question, Wzf, Whf, bhf,   // 2
                                           Wzb, Whb, bhb);
    conv_all_kernel<<<dim3(512, 10), 256>>>(Wzf, Whf, Wzb, Whb);      // 3

    const dim3 gg(TT / 128, 2);

    // ---- layer 0 fwd (A = x slice of xcat, lda=512, K=256) ----
    qrn_gemm_mma<0><<<gg, 256, GEMM_SMEM>>>(BF(pXh), BF(pXl), 512, 256,  // 4
                                            BF(pWz0fTh), BF(pWz0fTl),
                                            F32(pZp), nullptr, nullptr);
    qrn_gemm_mma<1><<<gg, 256, GEMM_SMEM>>>(BF(pXh), BF(pXl), 512, 256,
                                            BF(pWt0fTh), BF(pWt0fTl),
                                            F32(pZp), bzf, F32(pch0f));
    scan1_kernel<0><<<NC, DD>>>();
    scan2_kernel<0><<<8, 32>>>();
    scan3_fwd_kernel<<<NC, DD>>>();
    // ---- layer 0 bwd ----
    qrn_gemm_mma<0><<<gg, 256, GEMM_SMEM>>>(BF(pXh), BF(pXl), 512, 256,
                                            BF(pWz0bTh), BF(pWz0bTl),
                                            F32(pZp), nullptr, nullptr);
    qrn_gemm_mma<1><<<gg, 256, GEMM_SMEM>>>(BF(pXh), BF(pXl), 512, 256,
                                            BF(pWt0bTh), BF(pWt0bTl),
                                            F32(pZp), bzb, F32(pch0b));
    scan1_kernel<1><<<NC, DD>>>();
    scan2_kernel<1><<<8, 32>>>();
    scan3_bwd_conv_kernel<<<NC, DD>>>(story);  // q, xq hi/lo for layer 1

    // ---- layer 1 fwd ----
    qrn_gemm_mma<0><<<gg, 256, GEMM_SMEM>>>(
        BF(pQh), BF(pQl), 256, 256,
        BF(pWzTh) + 0 * DD * DD, BF(pWzTl) + 0 * DD * DD,
        F32(pZp), nullptr, nullptr);
    qrn_gemm_mma<1><<<gg, 256, GEMM_SMEM>>>(
        BF(pXh), BF(pXl), 512, 512,
        BF(pWhTh) + 0 * DD * 512, BF(pWhTl) + 0 * DD * 512,
        F32(pZp), bzf + DD, bhf + DD);
    scan1_kernel<0><<<NC, DD>>>();
    scan2_kernel<0><<<8, 32>>>();
    scan3_fwd_kernel<<<NC, DD>>>();
    // ---- layer 1 bwd ----
    qrn_gemm_mma<0><<<gg, 256, GEMM_SMEM>>>(
        BF(pQh), BF(pQl), 256, 256,
        BF(pWzTh) + 2 * DD * DD, BF(pWzTl) + 2 * DD * DD,
        F32(pZp), nullptr, nullptr);
    qrn_gemm_mma<1><<<gg, 256, GEMM_SMEM>>>(
        BF(pXh), BF(pXl), 512, 512,
        BF(pWhTh) + 2 * DD * 512, BF(pWhTl) + 2 * DD * 512,
        F32(pZp), bzb + DD, bhb + DD);
    scan1_kernel<1><<<NC, DD>>>();
    scan2_kernel<1><<<8, 32>>>();
    scan3_bwd_conv_kernel<<<NC, DD>>>(story);  // q, xq for layer 2

    // ---- layer 2 fwd (only h_fwd[T-1] needed) ----
    qrn_gemm_mma<0><<<gg, 256, GEMM_SMEM>>>(
        BF(pQh), BF(pQl), 256, 256,
        BF(pWzTh) + 1 * DD * DD, BF(pWzTl) + 1 * DD * DD,
        F32(pZp), nullptr, nullptr);
    qrn_gemm_mma<1><<<gg, 256, GEMM_SMEM>>>(
        BF(pXh), BF(pXl), 512, 512,
        BF(pWhTh) + 1 * DD * 512, BF(pWhTl) + 1 * DD * 512,
        F32(pZp), bzf + 2 * DD, bhf + 2 * DD);
    scan1_kernel<0><<<NC, DD>>>();
    final_kernel<<<8, 32>>>(out);
}